// round 2
// baseline (speedup 1.0000x reference)
#include <cuda_runtime.h>
#include <cstdint>

// Fused 2-layer LSTM + FC head for B=16384, T=10, IN=160, H=256.
// One CTA owns a 32-row batch tile for the whole network:
//   per step t: layer0 gates GEMM (K=416 over [x_t|h0]), state update,
//               layer1 gates GEMM (K=512 over [h0|h1]), state update,
//               FC partial accumulation with W_fc[t*H + :].
// All state (h0,h1 in smem A-buffer; c0,c1 in smem) stays on-chip for all 10 steps.
// Inner math uses packed fma.rn.f32x2 (2x fp32 FFMA throughput on sm_103a).

#define BT    32      // batch rows per CTA
#define ASTR  676     // A buffer row stride (160 x | 256 h0 | 256 h1 | 4 pad)
#define WTS   260     // W tile row stride (256 cols + 4 pad, keeps 16B alignment)
#define NTHR  256

typedef unsigned long long u64;

__device__ __forceinline__ u64 packdup(float x) {
    u64 r; asm("mov.b64 %0, {%1, %1};" : "=l"(r) : "f"(x)); return r;
}
__device__ __forceinline__ u64 pack2(float x, float y) {
    u64 r; asm("mov.b64 %0, {%1, %2};" : "=l"(r) : "f"(x), "f"(y)); return r;
}
__device__ __forceinline__ float2 unpack2(u64 v) {
    float2 f; asm("mov.b64 {%0, %1}, %2;" : "=f"(f.x), "=f"(f.y) : "l"(v)); return f;
}
__device__ __forceinline__ void fma2(u64& d, u64 a, u64 b) {
    asm("fma.rn.f32x2 %0, %1, %2, %0;" : "+l"(d) : "l"(a), "l"(b));
}
__device__ __forceinline__ float sigf(float x)  { return 1.0f / (1.0f + __expf(-x)); }
__device__ __forceinline__ float tanhf_(float x){ return 2.0f / (1.0f + __expf(-2.0f * x)) - 1.0f; }

// One LSTM layer step for this CTA's 32-row tile.
// KTOT: total reduction length; ABASE: starting column of this layer's input in A.
// KIN: boundary between feed-input weights (Wih) and recurrent weights (Whh).
// Output h values are stashed in registers (hstash) — caller writes them to A
// after a barrier, because A's h region is still being read during the passes.
template<int KTOT, int ABASE, int KIN>
__device__ __forceinline__ void lstm_layer_step(
    float* __restrict__ As, float* __restrict__ Wt, float* __restrict__ Cb,
    const float* __restrict__ Wih, const float* __restrict__ Whh,
    const float* __restrict__ bih, const float* __restrict__ bhh,
    int tid, int rg, int cg, int cboff,
    float (&hstash)[4][8])
{
    #pragma unroll
    for (int pass = 0; pass < 4; pass++) {
        const int jb = pass * 64;

        // init accumulators with (b_ih + b_hh) for this thread's 8 gate columns
        u64 acc[16];
        {
            float bs[8];
            #pragma unroll
            for (int mm = 0; mm < 8; mm++) {
                int gcol = (mm & 3) * 256 + jb + 2 * cg + (mm >> 2);
                bs[mm] = bih[gcol] + bhh[gcol];
            }
            u64 p0 = pack2(bs[0], bs[1]);
            u64 p1 = pack2(bs[2], bs[3]);
            u64 p2 = pack2(bs[4], bs[5]);
            u64 p3 = pack2(bs[6], bs[7]);
            #pragma unroll
            for (int i = 0; i < 4; i++) {
                acc[i * 4 + 0] = p0; acc[i * 4 + 1] = p1;
                acc[i * 4 + 2] = p2; acc[i * 4 + 3] = p3;
            }
        }

        for (int kb = 0; kb < KTOT; kb += 32) {
            __syncthreads();   // previous Wt tile consumers done
            // Cooperative load of W tile: Wt[k][m], m = interleaved (gate, hcol):
            //   gate = m&3, hcol = jb + (m>>2); gcol_global = gate*256 + hcol.
            {
                const int kq = tid & 7;       // k quad (4 floats each)
                const int mb = tid >> 3;      // base output column
                const int kglob = kb + kq * 4;
                const float* src;
                int stride, koff;
                if (kglob < KIN) { src = Wih; stride = KIN; koff = kglob; }
                else             { src = Whh; stride = 256; koff = kglob - KIN; }
                #pragma unroll
                for (int mi = 0; mi < 8; mi++) {
                    int m = mb + mi * 32;
                    int gcol = (m & 3) * 256 + jb + (m >> 2);
                    float4 v = *reinterpret_cast<const float4*>(src + gcol * stride + koff);
                    float* w = Wt + (kq * 4) * WTS + m;
                    w[0]       = v.x;
                    w[WTS]     = v.y;
                    w[2 * WTS] = v.z;
                    w[3 * WTS] = v.w;
                }
            }
            __syncthreads();

            const float* a0 = As + (rg * 4 + 0) * ASTR + ABASE + kb;
            const float* a1 = a0 + ASTR;
            const float* a2 = a1 + ASTR;
            const float* a3 = a2 + ASTR;
            const float* bsrc = Wt + cg * 8;

            #pragma unroll 8
            for (int kk = 0; kk < 32; kk++) {
                u64 ap0 = packdup(a0[kk]);
                u64 ap1 = packdup(a1[kk]);
                u64 ap2 = packdup(a2[kk]);
                u64 ap3 = packdup(a3[kk]);
                const u64* bp = reinterpret_cast<const u64*>(bsrc + kk * WTS);
                u64 b0 = bp[0], b1 = bp[1], b2 = bp[2], b3 = bp[3];
                fma2(acc[0],  ap0, b0); fma2(acc[1],  ap0, b1);
                fma2(acc[2],  ap0, b2); fma2(acc[3],  ap0, b3);
                fma2(acc[4],  ap1, b0); fma2(acc[5],  ap1, b1);
                fma2(acc[6],  ap1, b2); fma2(acc[7],  ap1, b3);
                fma2(acc[8],  ap2, b0); fma2(acc[9],  ap2, b1);
                fma2(acc[10], ap2, b2); fma2(acc[11], ap2, b3);
                fma2(acc[12], ap3, b0); fma2(acc[13], ap3, b1);
                fma2(acc[14], ap3, b2); fma2(acc[15], ap3, b3);
            }
        }

        // Epilogue: gate activations + cell update. Thread exclusively owns its
        // (row, hcol) cells, so c reads/writes need no barrier.
        #pragma unroll
        for (int i = 0; i < 4; i++) {
            const int r = rg * 4 + i;
            #pragma unroll
            for (int hh = 0; hh < 2; hh++) {
                float2 pif = unpack2(acc[i * 4 + 2 * hh]);      // (i, f)
                float2 pgo = unpack2(acc[i * 4 + 2 * hh + 1]);  // (g, o)
                float iv = sigf(pif.x);
                float fv = sigf(pif.y);
                float gv = tanhf_(pgo.x);
                float ov = sigf(pgo.y);
                int hcol = jb + 2 * cg + hh;
                float* cc = Cb + r * 512 + cboff + hcol;
                float c = fv * cc[0] + iv * gv;
                cc[0] = c;
                hstash[i][pass * 2 + hh] = ov * tanhf_(c);
            }
        }
    }
}

__global__ void __launch_bounds__(NTHR, 1)
lstm_fused_kernel(
    const float* __restrict__ x,
    const float* __restrict__ Wih0, const float* __restrict__ Whh0,
    const float* __restrict__ bih0, const float* __restrict__ bhh0,
    const float* __restrict__ Wih1, const float* __restrict__ Whh1,
    const float* __restrict__ bih1, const float* __restrict__ bhh1,
    const float* __restrict__ Wfc,  const float* __restrict__ bfc,
    float* __restrict__ out)
{
    extern __shared__ float sm[];
    float* As = sm;                         // [32][676]: x_t | h0 | h1
    float* Wt = As + BT * ASTR;             // [32][260]: K-tile of interleaved W cols
    float* Cb = Wt + 32 * WTS;              // [32][512]: c0 | c1

    const int tid = threadIdx.x;
    const int rg  = tid >> 5;               // warp id = row group (4 rows)
    const int cg  = tid & 31;               // lane = column group (2 h-cols x 4 gates)
    const int rbase = blockIdx.x * BT;

    // zero h/c state
    for (int idx = tid; idx < BT * ASTR; idx += NTHR) As[idx] = 0.0f;
    for (int idx = tid; idx < BT * 512;  idx += NTHR) Cb[idx] = 0.0f;
    __syncthreads();

    float hstash[4][8];
    float fcacc[4] = {0.0f, 0.0f, 0.0f, 0.0f};

    for (int t = 0; t < 10; t++) {
        // stage x_t tile: 32 rows x 160 cols (coalesced float4)
        for (int f = tid; f < BT * 40; f += NTHR) {
            int row = f / 40;
            int c4  = f % 40;
            float4 v = *reinterpret_cast<const float4*>(
                x + (size_t)(rbase + row) * 1600 + t * 160 + c4 * 4);
            *reinterpret_cast<float4*>(As + row * ASTR + c4 * 4) = v;
        }
        // (visibility of x stores is guaranteed by the sync inside the first
        //  Wt-tile load of layer 0)

        // ===== layer 0: K = 160(x) + 256(h0) =====
        lstm_layer_step<416, 0, 160>(As, Wt, Cb, Wih0, Whh0, bih0, bhh0,
                                     tid, rg, cg, 0, hstash);
        __syncthreads();   // everyone done reading old h0
        #pragma unroll
        for (int i = 0; i < 4; i++)
            #pragma unroll
            for (int p = 0; p < 4; p++)
                #pragma unroll
                for (int hh = 0; hh < 2; hh++)
                    As[(rg * 4 + i) * ASTR + 160 + p * 64 + 2 * cg + hh] =
                        hstash[i][p * 2 + hh];
        __syncthreads();

        // ===== layer 1: K = 256(h0) + 256(h1) =====
        lstm_layer_step<512, 160, 256>(As, Wt, Cb, Wih1, Whh1, bih1, bhh1,
                                       tid, rg, cg, 256, hstash);
        __syncthreads();   // everyone done reading old h1
        #pragma unroll
        for (int i = 0; i < 4; i++)
            #pragma unroll
            for (int p = 0; p < 4; p++)
                #pragma unroll
                for (int hh = 0; hh < 2; hh++) {
                    int hcol = p * 64 + 2 * cg + hh;
                    float h = hstash[i][p * 2 + hh];
                    As[(rg * 4 + i) * ASTR + 416 + hcol] = h;
                    fcacc[i] += h * Wfc[t * 256 + hcol];
                }
        __syncthreads();
    }

    // FC reduce across the warp (each warp owns 4 batch rows; lanes hold
    // partial sums over disjoint h-columns).
    #pragma unroll
    for (int i = 0; i < 4; i++) {
        #pragma unroll
        for (int off = 16; off > 0; off >>= 1)
            fcacc[i] += __shfl_xor_sync(0xffffffffu, fcacc[i], off);
    }
    if (cg == 0) {
        float bb = bfc[0];
        #pragma unroll
        for (int i = 0; i < 4; i++)
            out[rbase + rg * 4 + i] = sigf(fcacc[i] + bb);
    }
}

extern "C" void kernel_launch(void* const* d_in, const int* in_sizes, int n_in,
                              void* d_out, int out_size) {
    const float* x    = (const float*)d_in[0];
    const float* Wih0 = (const float*)d_in[1];
    const float* Whh0 = (const float*)d_in[2];
    const float* bih0 = (const float*)d_in[3];
    const float* bhh0 = (const float*)d_in[4];
    const float* Wih1 = (const float*)d_in[5];
    const float* Whh1 = (const float*)d_in[6];
    const float* bih1 = (const float*)d_in[7];
    const float* bhh1 = (const float*)d_in[8];
    const float* Wfc  = (const float*)d_in[9];
    const float* bfc  = (const float*)d_in[10];
    float* out = (float*)d_out;

    int B = in_sizes[0] / (10 * 160);
    int grid = B / BT;

    size_t shmem = (size_t)(BT * ASTR + 32 * WTS + BT * 512) * sizeof(float); // 185344 B
    cudaFuncSetAttribute(lstm_fused_kernel,
                         cudaFuncAttributeMaxDynamicSharedMemorySize, (int)shmem);

    lstm_fused_kernel<<<grid, NTHR, shmem>>>(
        x, Wih0, Whh0, bih0, bhh0, Wih1, Whh1, bih1, bhh1, Wfc, bfc, out);
}

// round 3
// speedup vs baseline: 1.7088x; 1.7088x over previous
#include <cuda_runtime.h>
#include <cstdint>

// Fused 2-layer LSTM + FC head. B=16384, T=10, IN=160, H=256.
// CTA = 32 batch rows. 8 warps: rg = wid&3 -> rows [8rg,8rg+8), ch = wid>>2
// -> 64-col half of the current 128-col pass tile. Each thread: 8 rows x
// 8 gate-cols (4 u64 pairs) of fma.rn.f32x2 accumulators.
// W tile in smem: 32k x 512m, segmented+XOR-swizzled so the transpose STS and
// the per-k LDS.64 B reads are both bank-conflict-free.

#define ASTR  676     // A row stride: 160 x | 256 h0 | 256 h1 | pad
#define WTS   514     // W tile row stride (floats)
#define NTHR  256

typedef unsigned long long u64;

__device__ __forceinline__ u64 packdup(float x) {
    u64 r; asm("mov.b64 %0, {%1, %1};" : "=l"(r) : "f"(x)); return r;
}
__device__ __forceinline__ u64 pack2(float x, float y) {
    u64 r; asm("mov.b64 %0, {%1, %2};" : "=l"(r) : "f"(x), "f"(y)); return r;
}
__device__ __forceinline__ float2 unpack2(u64 v) {
    float2 f; asm("mov.b64 {%0, %1}, %2;" : "=f"(f.x), "=f"(f.y) : "l"(v)); return f;
}
__device__ __forceinline__ void fma2(u64& d, u64 a, u64 b) {
    asm("fma.rn.f32x2 %0, %1, %2, %0;" : "+l"(d) : "l"(a), "l"(b));
}
__device__ __forceinline__ float tanh_ap(float x) {
    float y; asm("tanh.approx.f32 %0, %1;" : "=f"(y) : "f"(x)); return y;
}
__device__ __forceinline__ float sigf(float x) {
    return fmaf(0.5f, tanh_ap(0.5f * x), 0.5f);
}
__device__ __forceinline__ float f4c(const float4& v, int c) {
    return c == 0 ? v.x : (c == 1 ? v.y : (c == 2 ? v.z : v.w));
}

// One LSTM layer step (both output-column passes) for this CTA's 32-row tile.
template<int KTOT, int ABASE, int KIN>
__device__ __forceinline__ void lstm_layer_step(
    float* __restrict__ As, float* __restrict__ Wt, float* __restrict__ Cb,
    const float* __restrict__ Wih, const float* __restrict__ Whh,
    const float* __restrict__ bih, const float* __restrict__ bhh,
    int tid, int rg, int ch, int cg, int cboff,
    float (&hstA)[8][2], float (&hstB)[8][2])
{
    for (int p = 0; p < 2; p++) {
        const int jb = p * 128;

        // ---- init accumulators with biases ----
        u64 acc[32];
        {
            u64 pq[4];
            #pragma unroll
            for (int q = 0; q < 4; q++) {
                int hc = jb + ch * 64 + 2 * cg + (q >> 1);
                int g0 = ((q & 1) * 2) * 256 + hc;
                int g1 = g0 + 256;
                pq[q] = pack2(bih[g0] + bhh[g0], bih[g1] + bhh[g1]);
            }
            #pragma unroll
            for (int i = 0; i < 8; i++)
                #pragma unroll
                for (int q = 0; q < 4; q++)
                    acc[i * 4 + q] = pq[q];
        }

        // ---- K loop ----
        for (int kb = 0; kb < KTOT; kb += 32) {
            __syncthreads();   // previous tile's consumers done
            {   // cooperative W-tile load: 32k x 512m, transposed + swizzled
                const int kq2 = tid & 7;    // k-quad
                const int mb  = tid >> 3;   // m base (0..31)
                const int kglob = kb + kq2 * 4;
                const float* src; int stride, koff;
                if (kglob < KIN) { src = Wih; stride = KIN; koff = kglob; }
                else             { src = Whh; stride = 256; koff = kglob - KIN; }
                #pragma unroll
                for (int mi = 0; mi < 16; mi++) {
                    int m   = mb + mi * 32;
                    int seg = m >> 6;             // 0..7
                    int q   = seg & 3, chq = seg >> 2;
                    int e   = m & 63;
                    int cgl = e >> 1, j = e & 1;
                    int gate = (q & 1) * 2 + j;
                    int gcol = gate * 256 + jb + chq * 64 + 2 * cgl + (q >> 1);
                    float4 v = *reinterpret_cast<const float4*>(
                        src + (size_t)gcol * stride + koff);
                    int msw = m ^ (kq2 << 2);     // store swizzle
                    float* w = Wt + (kq2 * 4) * WTS + msw;
                    w[0]       = v.x;
                    w[WTS]     = v.y;
                    w[2 * WTS] = v.z;
                    w[3 * WTS] = v.w;
                }
            }
            __syncthreads();

            const float* ab = As + (rg * 8) * ASTR + ABASE + kb;
            #pragma unroll 2
            for (int kq = 0; kq < 8; kq++) {
                float4 av[8];
                #pragma unroll
                for (int i = 0; i < 8; i++)
                    av[i] = *reinterpret_cast<const float4*>(ab + i * ASTR + kq * 4);
                #pragma unroll
                for (int c = 0; c < 4; c++) {
                    const int kk = kq * 4 + c;
                    const u64* bp = reinterpret_cast<const u64*>(
                        Wt + kk * WTS + ch * 256) + (cg ^ (kq << 1));
                    u64 b0 = bp[0], b1 = bp[32], b2 = bp[64], b3 = bp[96];
                    #pragma unroll
                    for (int i = 0; i < 8; i++) {
                        u64 ap = packdup(f4c(av[i], c));
                        fma2(acc[i * 4 + 0], ap, b0);
                        fma2(acc[i * 4 + 1], ap, b1);
                        fma2(acc[i * 4 + 2], ap, b2);
                        fma2(acc[i * 4 + 3], ap, b3);
                    }
                }
            }
        }

        // ---- epilogue: activations + cell update (exclusive ownership) ----
        #pragma unroll
        for (int i = 0; i < 8; i++) {
            const int r = rg * 8 + i;
            #pragma unroll
            for (int hh = 0; hh < 2; hh++) {
                float2 pif = unpack2(acc[i * 4 + 2 * hh]);      // (i, f)
                float2 pgo = unpack2(acc[i * 4 + 2 * hh + 1]);  // (g, o)
                float iv = sigf(pif.x);
                float fv = sigf(pif.y);
                float gv = tanh_ap(pgo.x);
                float ov = sigf(pgo.y);
                int hcol = jb + ch * 64 + 2 * cg + hh;
                float* cc = Cb + r * 512 + cboff + hcol;
                float c = fv * cc[0] + iv * gv;
                cc[0] = c;
                float h = ov * tanh_ap(c);
                if (p == 0) hstA[i][hh] = h; else hstB[i][hh] = h;
            }
        }
    }
}

__global__ void __launch_bounds__(NTHR, 1)
lstm_fused_kernel(
    const float* __restrict__ x,
    const float* __restrict__ Wih0, const float* __restrict__ Whh0,
    const float* __restrict__ bih0, const float* __restrict__ bhh0,
    const float* __restrict__ Wih1, const float* __restrict__ Whh1,
    const float* __restrict__ bih1, const float* __restrict__ bhh1,
    const float* __restrict__ Wfc,  const float* __restrict__ bfc,
    float* __restrict__ out)
{
    extern __shared__ float sm[];
    float* As = sm;                      // [32][676]
    float* Wt = As + 32 * ASTR;          // [32][514]
    float* Cb = Wt + 32 * WTS;           // [32][512]: c0 | c1
    float* Fp = Cb + 32 * 512;           // [32][2] FC partials

    const int tid = threadIdx.x;
    const int wid = tid >> 5;
    const int rg  = wid & 3;             // row group: rows [8rg, 8rg+8)
    const int ch  = wid >> 2;            // column half within 128-col pass
    const int cg  = tid & 31;
    const int rbase = blockIdx.x * 32;

    for (int idx = tid; idx < 32 * ASTR; idx += NTHR) As[idx] = 0.0f;
    for (int idx = tid; idx < 32 * 512;  idx += NTHR) Cb[idx] = 0.0f;
    __syncthreads();

    float hstA[8][2], hstB[8][2];
    float fcacc[8];
    #pragma unroll
    for (int i = 0; i < 8; i++) fcacc[i] = 0.0f;

    for (int t = 0; t < 10; t++) {
        // stage x_t: 32 rows x 160 cols
        for (int f = tid; f < 32 * 40; f += NTHR) {
            int row = f / 40, c4 = f % 40;
            float4 v = *reinterpret_cast<const float4*>(
                x + (size_t)(rbase + row) * 1600 + t * 160 + c4 * 4);
            *reinterpret_cast<float4*>(As + row * ASTR + c4 * 4) = v;
        }
        // visibility: first barrier inside layer0's kb loop

        // ===== layer 0: K = 160(x) + 256(h0) =====
        lstm_layer_step<416, 0, 160>(As, Wt, Cb, Wih0, Whh0, bih0, bhh0,
                                     tid, rg, ch, cg, 0, hstA, hstB);
        __syncthreads();   // all warps done reading old h0
        #pragma unroll
        for (int i = 0; i < 8; i++) {
            int r = rg * 8 + i;
            *reinterpret_cast<float2*>(As + r * ASTR + 160 + ch * 64 + 2 * cg) =
                make_float2(hstA[i][0], hstA[i][1]);
            *reinterpret_cast<float2*>(As + r * ASTR + 160 + 128 + ch * 64 + 2 * cg) =
                make_float2(hstB[i][0], hstB[i][1]);
        }
        __syncthreads();

        // ===== layer 1: K = 256(h0) + 256(h1) =====
        lstm_layer_step<512, 160, 256>(As, Wt, Cb, Wih1, Whh1, bih1, bhh1,
                                       tid, rg, ch, cg, 256, hstA, hstB);
        __syncthreads();   // all warps done reading old h1
        {
            float2 w0 = *reinterpret_cast<const float2*>(
                Wfc + t * 256 + ch * 64 + 2 * cg);
            float2 w1 = *reinterpret_cast<const float2*>(
                Wfc + t * 256 + 128 + ch * 64 + 2 * cg);
            #pragma unroll
            for (int i = 0; i < 8; i++) {
                int r = rg * 8 + i;
                *reinterpret_cast<float2*>(As + r * ASTR + 416 + ch * 64 + 2 * cg) =
                    make_float2(hstA[i][0], hstA[i][1]);
                *reinterpret_cast<float2*>(As + r * ASTR + 416 + 128 + ch * 64 + 2 * cg) =
                    make_float2(hstB[i][0], hstB[i][1]);
                fcacc[i] += hstA[i][0] * w0.x + hstA[i][1] * w0.y
                          + hstB[i][0] * w1.x + hstB[i][1] * w1.y;
            }
        }
        __syncthreads();
    }

    // FC reduce: lanes of a warp cover disjoint cols for the warp's 8 rows.
    #pragma unroll
    for (int i = 0; i < 8; i++) {
        #pragma unroll
        for (int off = 16; off > 0; off >>= 1)
            fcacc[i] += __shfl_xor_sync(0xffffffffu, fcacc[i], off);
    }
    if (cg == 0) {
        #pragma unroll
        for (int i = 0; i < 8; i++)
            Fp[(rg * 8 + i) * 2 + ch] = fcacc[i];
    }
    __syncthreads();
    if (tid < 32) {
        float v = Fp[tid * 2] + Fp[tid * 2 + 1] + bfc[0];
        out[rbase + tid] = sigf(v);
    }
}

extern "C" void kernel_launch(void* const* d_in, const int* in_sizes, int n_in,
                              void* d_out, int out_size) {
    const float* x    = (const float*)d_in[0];
    const float* Wih0 = (const float*)d_in[1];
    const float* Whh0 = (const float*)d_in[2];
    const float* bih0 = (const float*)d_in[3];
    const float* bhh0 = (const float*)d_in[4];
    const float* Wih1 = (const float*)d_in[5];
    const float* Whh1 = (const float*)d_in[6];
    const float* bih1 = (const float*)d_in[7];
    const float* bhh1 = (const float*)d_in[8];
    const float* Wfc  = (const float*)d_in[9];
    const float* bfc  = (const float*)d_in[10];
    float* out = (float*)d_out;

    int B = in_sizes[0] / (10 * 160);
    int grid = B / 32;

    size_t shmem = (size_t)(32 * ASTR + 32 * WTS + 32 * 512 + 64) * sizeof(float); // 218368 B
    cudaFuncSetAttribute(lstm_fused_kernel,
                         cudaFuncAttributeMaxDynamicSharedMemorySize, (int)shmem);

    lstm_fused_kernel<<<grid, NTHR, shmem>>>(
        x, Wih0, Whh0, bih0, bhh0, Wih1, Whh1, bih1, bhh1, Wfc, bfc, out);
}

// round 4
// speedup vs baseline: 1.7098x; 1.0006x over previous
#include <cuda_runtime.h>
#include <cstdint>

// Fused 2-layer LSTM + FC head. B=16384, T=10, IN=160, H=256.
// CTA = 32 batch rows. 8 warps: rg = wid&3 -> rows [8rg,8rg+8), ch = wid>>2
// -> 64-col half of the current 128-col pass tile. Each thread: 8 rows x
// 8 gate-cols (4 u64 pairs) of fma.rn.f32x2 accumulators.
// W tile in smem: 32k x 512m, segmented+XOR-swizzled so the transpose STS and
// the per-k LDS.64 B reads are both bank-conflict-free.

#define ASTR  676     // A row stride: 160 x | 256 h0 | 256 h1 | pad
#define WTS   514     // W tile row stride (floats)
#define NTHR  256

typedef unsigned long long u64;

__device__ __forceinline__ u64 packdup(float x) {
    u64 r; asm("mov.b64 %0, {%1, %1};" : "=l"(r) : "f"(x)); return r;
}
__device__ __forceinline__ u64 pack2(float x, float y) {
    u64 r; asm("mov.b64 %0, {%1, %2};" : "=l"(r) : "f"(x), "f"(y)); return r;
}
__device__ __forceinline__ float2 unpack2(u64 v) {
    float2 f; asm("mov.b64 {%0, %1}, %2;" : "=f"(f.x), "=f"(f.y) : "l"(v)); return f;
}
__device__ __forceinline__ void fma2(u64& d, u64 a, u64 b) {
    asm("fma.rn.f32x2 %0, %1, %2, %0;" : "+l"(d) : "l"(a), "l"(b));
}
__device__ __forceinline__ float tanh_ap(float x) {
    float y; asm("tanh.approx.f32 %0, %1;" : "=f"(y) : "f"(x)); return y;
}
__device__ __forceinline__ float sigf(float x) {
    return fmaf(0.5f, tanh_ap(0.5f * x), 0.5f);
}
__device__ __forceinline__ float f4c(const float4& v, int c) {
    return c == 0 ? v.x : (c == 1 ? v.y : (c == 2 ? v.z : v.w));
}

// One LSTM layer step (both output-column passes) for this CTA's 32-row tile.
template<int KTOT, int ABASE, int KIN>
__device__ __forceinline__ void lstm_layer_step(
    float* __restrict__ As, float* __restrict__ Wt, float* __restrict__ Cb,
    const float* __restrict__ Wih, const float* __restrict__ Whh,
    const float* __restrict__ bih, const float* __restrict__ bhh,
    int tid, int rg, int ch, int cg, int cboff,
    float (&hstA)[8][2], float (&hstB)[8][2])
{
    for (int p = 0; p < 2; p++) {
        const int jb = p * 128;

        // ---- init accumulators with biases ----
        u64 acc[32];
        {
            u64 pq[4];
            #pragma unroll
            for (int q = 0; q < 4; q++) {
                int hc = jb + ch * 64 + 2 * cg + (q >> 1);
                int g0 = ((q & 1) * 2) * 256 + hc;
                int g1 = g0 + 256;
                pq[q] = pack2(bih[g0] + bhh[g0], bih[g1] + bhh[g1]);
            }
            #pragma unroll
            for (int i = 0; i < 8; i++)
                #pragma unroll
                for (int q = 0; q < 4; q++)
                    acc[i * 4 + q] = pq[q];
        }

        // ---- K loop ----
        for (int kb = 0; kb < KTOT; kb += 32) {
            __syncthreads();   // previous tile's consumers done
            {   // cooperative W-tile load: 32k x 512m, transposed + swizzled
                const int kq2 = tid & 7;    // k-quad
                const int mb  = tid >> 3;   // m base (0..31)
                const int kglob = kb + kq2 * 4;
                const float* src; int stride, koff;
                if (kglob < KIN) { src = Wih; stride = KIN; koff = kglob; }
                else             { src = Whh; stride = 256; koff = kglob - KIN; }
                #pragma unroll
                for (int mi = 0; mi < 16; mi++) {
                    int m   = mb + mi * 32;
                    int seg = m >> 6;             // 0..7
                    int q   = seg & 3, chq = seg >> 2;
                    int e   = m & 63;
                    int cgl = e >> 1, j = e & 1;
                    int gate = (q & 1) * 2 + j;
                    int gcol = gate * 256 + jb + chq * 64 + 2 * cgl + (q >> 1);
                    float4 v = *reinterpret_cast<const float4*>(
                        src + (size_t)gcol * stride + koff);
                    int msw = m ^ (kq2 << 2);     // store swizzle
                    float* w = Wt + (kq2 * 4) * WTS + msw;
                    w[0]       = v.x;
                    w[WTS]     = v.y;
                    w[2 * WTS] = v.z;
                    w[3 * WTS] = v.w;
                }
            }
            __syncthreads();

            const float* ab = As + (rg * 8) * ASTR + ABASE + kb;
            #pragma unroll 2
            for (int kq = 0; kq < 8; kq++) {
                float4 av[8];
                #pragma unroll
                for (int i = 0; i < 8; i++)
                    av[i] = *reinterpret_cast<const float4*>(ab + i * ASTR + kq * 4);
                #pragma unroll
                for (int c = 0; c < 4; c++) {
                    const int kk = kq * 4 + c;
                    const u64* bp = reinterpret_cast<const u64*>(
                        Wt + kk * WTS + ch * 256) + (cg ^ (kq << 1));
                    u64 b0 = bp[0], b1 = bp[32], b2 = bp[64], b3 = bp[96];
                    #pragma unroll
                    for (int i = 0; i < 8; i++) {
                        u64 ap = packdup(f4c(av[i], c));
                        fma2(acc[i * 4 + 0], ap, b0);
                        fma2(acc[i * 4 + 1], ap, b1);
                        fma2(acc[i * 4 + 2], ap, b2);
                        fma2(acc[i * 4 + 3], ap, b3);
                    }
                }
            }
        }

        // ---- epilogue: activations + cell update (exclusive ownership) ----
        #pragma unroll
        for (int i = 0; i < 8; i++) {
            const int r = rg * 8 + i;
            #pragma unroll
            for (int hh = 0; hh < 2; hh++) {
                float2 pif = unpack2(acc[i * 4 + 2 * hh]);      // (i, f)
                float2 pgo = unpack2(acc[i * 4 + 2 * hh + 1]);  // (g, o)
                float iv = sigf(pif.x);
                float fv = sigf(pif.y);
                float gv = tanh_ap(pgo.x);
                float ov = sigf(pgo.y);
                int hcol = jb + ch * 64 + 2 * cg + hh;
                float* cc = Cb + r * 512 + cboff + hcol;
                float c = fv * cc[0] + iv * gv;
                cc[0] = c;
                float h = ov * tanh_ap(c);
                if (p == 0) hstA[i][hh] = h; else hstB[i][hh] = h;
            }
        }
    }
}

__global__ void __launch_bounds__(NTHR, 1)
lstm_fused_kernel(
    const float* __restrict__ x,
    const float* __restrict__ Wih0, const float* __restrict__ Whh0,
    const float* __restrict__ bih0, const float* __restrict__ bhh0,
    const float* __restrict__ Wih1, const float* __restrict__ Whh1,
    const float* __restrict__ bih1, const float* __restrict__ bhh1,
    const float* __restrict__ Wfc,  const float* __restrict__ bfc,
    float* __restrict__ out)
{
    extern __shared__ float sm[];
    float* As = sm;                      // [32][676]
    float* Wt = As + 32 * ASTR;          // [32][514]
    float* Cb = Wt + 32 * WTS;           // [32][512]: c0 | c1
    float* Fp = Cb + 32 * 512;           // [32][2] FC partials

    const int tid = threadIdx.x;
    const int wid = tid >> 5;
    const int rg  = wid & 3;             // row group: rows [8rg, 8rg+8)
    const int ch  = wid >> 2;            // column half within 128-col pass
    const int cg  = tid & 31;
    const int rbase = blockIdx.x * 32;

    for (int idx = tid; idx < 32 * ASTR; idx += NTHR) As[idx] = 0.0f;
    for (int idx = tid; idx < 32 * 512;  idx += NTHR) Cb[idx] = 0.0f;
    __syncthreads();

    float hstA[8][2], hstB[8][2];
    float fcacc[8];
    #pragma unroll
    for (int i = 0; i < 8; i++) fcacc[i] = 0.0f;

    for (int t = 0; t < 10; t++) {
        // stage x_t: 32 rows x 160 cols
        for (int f = tid; f < 32 * 40; f += NTHR) {
            int row = f / 40, c4 = f % 40;
            float4 v = *reinterpret_cast<const float4*>(
                x + (size_t)(rbase + row) * 1600 + t * 160 + c4 * 4);
            *reinterpret_cast<float4*>(As + row * ASTR + c4 * 4) = v;
        }
        // visibility: first barrier inside layer0's kb loop

        // ===== layer 0: K = 160(x) + 256(h0) =====
        lstm_layer_step<416, 0, 160>(As, Wt, Cb, Wih0, Whh0, bih0, bhh0,
                                     tid, rg, ch, cg, 0, hstA, hstB);
        __syncthreads();   // all warps done reading old h0
        #pragma unroll
        for (int i = 0; i < 8; i++) {
            int r = rg * 8 + i;
            *reinterpret_cast<float2*>(As + r * ASTR + 160 + ch * 64 + 2 * cg) =
                make_float2(hstA[i][0], hstA[i][1]);
            *reinterpret_cast<float2*>(As + r * ASTR + 160 + 128 + ch * 64 + 2 * cg) =
                make_float2(hstB[i][0], hstB[i][1]);
        }
        __syncthreads();

        // ===== layer 1: K = 256(h0) + 256(h1) =====
        lstm_layer_step<512, 160, 256>(As, Wt, Cb, Wih1, Whh1, bih1, bhh1,
                                       tid, rg, ch, cg, 256, hstA, hstB);
        __syncthreads();   // all warps done reading old h1
        {
            float2 w0 = *reinterpret_cast<const float2*>(
                Wfc + t * 256 + ch * 64 + 2 * cg);
            float2 w1 = *reinterpret_cast<const float2*>(
                Wfc + t * 256 + 128 + ch * 64 + 2 * cg);
            #pragma unroll
            for (int i = 0; i < 8; i++) {
                int r = rg * 8 + i;
                *reinterpret_cast<float2*>(As + r * ASTR + 416 + ch * 64 + 2 * cg) =
                    make_float2(hstA[i][0], hstA[i][1]);
                *reinterpret_cast<float2*>(As + r * ASTR + 416 + 128 + ch * 64 + 2 * cg) =
                    make_float2(hstB[i][0], hstB[i][1]);
                fcacc[i] += hstA[i][0] * w0.x + hstA[i][1] * w0.y
                          + hstB[i][0] * w1.x + hstB[i][1] * w1.y;
            }
        }
        __syncthreads();
    }

    // FC reduce: lanes of a warp cover disjoint cols for the warp's 8 rows.
    #pragma unroll
    for (int i = 0; i < 8; i++) {
        #pragma unroll
        for (int off = 16; off > 0; off >>= 1)
            fcacc[i] += __shfl_xor_sync(0xffffffffu, fcacc[i], off);
    }
    if (cg == 0) {
        #pragma unroll
        for (int i = 0; i < 8; i++)
            Fp[(rg * 8 + i) * 2 + ch] = fcacc[i];
    }
    __syncthreads();
    if (tid < 32) {
        float v = Fp[tid * 2] + Fp[tid * 2 + 1] + bfc[0];
        out[rbase + tid] = sigf(v);
    }
}

extern "C" void kernel_launch(void* const* d_in, const int* in_sizes, int n_in,
                              void* d_out, int out_size) {
    const float* x    = (const float*)d_in[0];
    const float* Wih0 = (const float*)d_in[1];
    const float* Whh0 = (const float*)d_in[2];
    const float* bih0 = (const float*)d_in[3];
    const float* bhh0 = (const float*)d_in[4];
    const float* Wih1 = (const float*)d_in[5];
    const float* Whh1 = (const float*)d_in[6];
    const float* bih1 = (const float*)d_in[7];
    const float* bhh1 = (const float*)d_in[8];
    const float* Wfc  = (const float*)d_in[9];
    const float* bfc  = (const float*)d_in[10];
    float* out = (float*)d_out;

    int B = in_sizes[0] / (10 * 160);
    int grid = B / 32;

    size_t shmem = (size_t)(32 * ASTR + 32 * WTS + 32 * 512 + 64) * sizeof(float); // 218368 B
    cudaFuncSetAttribute(lstm_fused_kernel,
                         cudaFuncAttributeMaxDynamicSharedMemorySize, (int)shmem);

    lstm_fused_kernel<<<grid, NTHR, shmem>>>(
        x, Wih0, Whh0, bih0, bhh0, Wih1, Whh1, bih1, bhh1, Wfc, bfc, out);
}

// round 5
// speedup vs baseline: 2.2671x; 1.3259x over previous
#include <cuda_runtime.h>
#include <cstdint>

// Fused 2-layer LSTM + FC head. B=16384, T=10, IN=160, H=256.
// CTA = 32 batch rows, 256 threads. Weights are pre-transposed once per launch
// into Wprep (device global) in the exact smem-tile image the compute loop
// consumes, then streamed tile-by-tile with double-buffered cp.async.cg.
// Inner math: packed fma.rn.f32x2, 8 rows x 8 gate-cols per thread.

#define ASTR  676                 // A row stride: 160 x | 256 h0 | 256 h1 | pad
#define WTS2  520                 // W tile row stride (16B-aligned: 2080 B)
#define TK    16                  // k rows per tile
#define TILE_FLOATS (TK * WTS2)   // 8320 floats = 33280 B
#define TILE_CHUNKS (TILE_FLOATS / 4)  // 2080 x 16B
#define NTILES 116                // 26+26+32+32 per step
#define NTHR  256

__device__ __align__(16) float Wprep[NTILES * TILE_FLOATS];
__device__ float Bsum[2048];

typedef unsigned long long u64;

__device__ __forceinline__ u64 packdup(float x) {
    u64 r; asm("mov.b64 %0, {%1, %1};" : "=l"(r) : "f"(x)); return r;
}
__device__ __forceinline__ u64 pack2(float x, float y) {
    u64 r; asm("mov.b64 %0, {%1, %2};" : "=l"(r) : "f"(x), "f"(y)); return r;
}
__device__ __forceinline__ float2 unpack2(u64 v) {
    float2 f; asm("mov.b64 {%0, %1}, %2;" : "=f"(f.x), "=f"(f.y) : "l"(v)); return f;
}
__device__ __forceinline__ void fma2(u64& d, u64 a, u64 b) {
    asm("fma.rn.f32x2 %0, %1, %2, %0;" : "+l"(d) : "l"(a), "l"(b));
}
__device__ __forceinline__ float tanh_ap(float x) {
    float y; asm("tanh.approx.f32 %0, %1;" : "=f"(y) : "f"(x)); return y;
}
__device__ __forceinline__ float sigf(float x) {
    return fmaf(0.5f, tanh_ap(0.5f * x), 0.5f);
}
__device__ __forceinline__ float f4c(const float4& v, int c) {
    return c == 0 ? v.x : (c == 1 ? v.y : (c == 2 ? v.z : v.w));
}
__device__ __forceinline__ uint32_t smem_u32(const void* p) {
    uint32_t a;
    asm("{ .reg .u64 t; cvta.to.shared.u64 t, %1; cvt.u32.u64 %0, t; }"
        : "=r"(a) : "l"(p));
    return a;
}

// ---------------- prep kernels (run once per launch) ----------------

__global__ void prep_weights(const float* __restrict__ Wih0,
                             const float* __restrict__ Whh0,
                             const float* __restrict__ Wih1,
                             const float* __restrict__ Whh1) {
    int idx = blockIdx.x * blockDim.x + threadIdx.x;
    if (idx >= NTILES * TK * 512) return;
    int m  = idx & 511;
    int kk = (idx >> 9) & 15;
    int ti = idx >> 13;

    int layer, jb, kb;
    if      (ti < 26) { layer = 0; jb = 0;   kb = ti * 16; }
    else if (ti < 52) { layer = 0; jb = 128; kb = (ti - 26) * 16; }
    else if (ti < 84) { layer = 1; jb = 0;   kb = (ti - 52) * 16; }
    else              { layer = 1; jb = 128; kb = (ti - 84) * 16; }

    int seg = m >> 6, q = seg & 3, chq = seg >> 2;
    int e = m & 63, cgl = e >> 1, j = e & 1;
    int gate = (q & 1) * 2 + j;
    int gcol = gate * 256 + jb + chq * 64 + 2 * cgl + (q >> 1);
    int kglob = kb + kk;

    float v;
    if (layer == 0)
        v = (kglob < 160) ? Wih0[gcol * 160 + kglob]
                          : Whh0[gcol * 256 + (kglob - 160)];
    else
        v = (kglob < 256) ? Wih1[gcol * 256 + kglob]
                          : Whh1[gcol * 256 + (kglob - 256)];
    Wprep[(size_t)ti * TILE_FLOATS + kk * WTS2 + m] = v;
}

__global__ void prep_bias(const float* __restrict__ bih0, const float* __restrict__ bhh0,
                          const float* __restrict__ bih1, const float* __restrict__ bhh1) {
    int i = blockIdx.x * blockDim.x + threadIdx.x;
    if (i < 1024)      Bsum[i] = bih0[i] + bhh0[i];
    else if (i < 2048) Bsum[i] = bih1[i - 1024] + bhh1[i - 1024];
}

// ---------------- main kernel ----------------

__device__ __forceinline__ void issue_tile(uint32_t wtb_u32, int buf, int tile, int tid) {
    const float* src = Wprep + (size_t)tile * TILE_FLOATS;
    uint32_t dst = wtb_u32 + (uint32_t)buf * (TILE_FLOATS * 4);
    #pragma unroll
    for (int c = 0; c < 9; c++) {
        int off = tid + c * NTHR;
        if (off < TILE_CHUNKS) {
            asm volatile("cp.async.cg.shared.global [%0], [%1], 16;"
                :: "r"(dst + (uint32_t)off * 16), "l"(src + off * 4) : "memory");
        }
    }
    asm volatile("cp.async.commit_group;" ::: "memory");
}

// One output-column pass (128 gate-cols x 4 gates) of one LSTM layer.
template<int KTOT, int ABASE>
__device__ __forceinline__ void layer_pass(
    const float* __restrict__ As, float* __restrict__ Cb,
    const float* __restrict__ WtB, uint32_t wtb_u32,
    int bsoff, int jb, int cboff,
    int tid, int rg, int ch, int cg,
    int& next, int& buf, float (&hst)[8][2])
{
    u64 acc[32];
    {
        u64 pq[4];
        #pragma unroll
        for (int q = 0; q < 4; q++) {
            int hc = jb + ch * 64 + 2 * cg + (q >> 1);
            int g0 = ((q & 1) * 2) * 256 + hc;
            pq[q] = pack2(Bsum[bsoff + g0], Bsum[bsoff + g0 + 256]);
        }
        #pragma unroll
        for (int i = 0; i < 8; i++)
            #pragma unroll
            for (int q = 0; q < 4; q++)
                acc[i * 4 + q] = pq[q];
    }

    const float* ab0 = As + (rg * 8) * ASTR + ABASE;
    const float* wb0 = WtB + ch * 256 + 2 * cg;

    for (int kb = 0; kb < KTOT; kb += TK) {
        asm volatile("cp.async.wait_group 0;" ::: "memory");
        __syncthreads();                       // tile[buf] ready; prev compute done
        issue_tile(wtb_u32, buf ^ 1, next, tid);
        next = (next + 1 == NTILES) ? 0 : next + 1;

        const float* wbase = wb0 + buf * TILE_FLOATS;
        const float* ab = ab0 + kb;
        #pragma unroll
        for (int kq = 0; kq < 4; kq++) {
            float4 av[8];
            #pragma unroll
            for (int i = 0; i < 8; i++)
                av[i] = *reinterpret_cast<const float4*>(ab + i * ASTR + kq * 4);
            #pragma unroll
            for (int c = 0; c < 4; c++) {
                const u64* bp = reinterpret_cast<const u64*>(wbase + (kq * 4 + c) * WTS2);
                u64 b0 = bp[0], b1 = bp[32], b2 = bp[64], b3 = bp[96];
                #pragma unroll
                for (int i = 0; i < 8; i++) {
                    u64 ap = packdup(f4c(av[i], c));
                    fma2(acc[i * 4 + 0], ap, b0);
                    fma2(acc[i * 4 + 1], ap, b1);
                    fma2(acc[i * 4 + 2], ap, b2);
                    fma2(acc[i * 4 + 3], ap, b3);
                }
            }
        }
        buf ^= 1;
    }

    // epilogue: activations + cell update (exclusive (row,hcol) ownership)
    #pragma unroll
    for (int i = 0; i < 8; i++) {
        const int r = rg * 8 + i;
        #pragma unroll
        for (int hh = 0; hh < 2; hh++) {
            float2 pif = unpack2(acc[i * 4 + 2 * hh]);      // (i, f)
            float2 pgo = unpack2(acc[i * 4 + 2 * hh + 1]);  // (g, o)
            float iv = sigf(pif.x);
            float fv = sigf(pif.y);
            float gv = tanh_ap(pgo.x);
            float ov = sigf(pgo.y);
            int hcol = jb + ch * 64 + 2 * cg + hh;
            float* cc = Cb + r * 512 + cboff + hcol;
            float c = fv * cc[0] + iv * gv;
            cc[0] = c;
            hst[i][hh] = ov * tanh_ap(c);
        }
    }
}

__global__ void __launch_bounds__(NTHR, 1)
lstm_fused_kernel(
    const float* __restrict__ x,
    const float* __restrict__ Wfc, const float* __restrict__ bfc,
    float* __restrict__ out)
{
    extern __shared__ float sm[];
    float* As  = sm;                        // [32][676]
    float* Cb  = As + 32 * ASTR;            // [32][512] c0|c1
    float* WtB = Cb + 32 * 512;             // 2 x tile
    float* Fp  = WtB + 2 * TILE_FLOATS;     // [32][2]

    const int tid = threadIdx.x;
    const int wid = tid >> 5;
    const int rg  = wid & 3;
    const int ch  = wid >> 2;
    const int cg  = tid & 31;
    const int rbase = blockIdx.x * 32;
    const uint32_t wtb_u32 = smem_u32(WtB);

    int next = 1, buf = 0;
    issue_tile(wtb_u32, 0, 0, tid);        // prologue prefetch of tile 0

    for (int idx = tid; idx < 32 * ASTR; idx += NTHR) As[idx] = 0.0f;
    for (int idx = tid; idx < 32 * 512;  idx += NTHR) Cb[idx] = 0.0f;
    __syncthreads();

    float hstA[8][2], hstB[8][2];
    float fcacc[8];
    #pragma unroll
    for (int i = 0; i < 8; i++) fcacc[i] = 0.0f;

    for (int t = 0; t < 10; t++) {
        // stage x_t (coalesced; made visible by first in-loop barrier)
        for (int f = tid; f < 32 * 40; f += NTHR) {
            int row = f / 40, c4 = f % 40;
            float4 v = *reinterpret_cast<const float4*>(
                x + (size_t)(rbase + row) * 1600 + t * 160 + c4 * 4);
            *reinterpret_cast<float4*>(As + row * ASTR + c4 * 4) = v;
        }

        // ===== layer 0 (K = 160 x + 256 h0) =====
        layer_pass<416, 0>(As, Cb, WtB, wtb_u32, 0, 0,   0, tid, rg, ch, cg, next, buf, hstA);
        layer_pass<416, 0>(As, Cb, WtB, wtb_u32, 0, 128, 0, tid, rg, ch, cg, next, buf, hstB);
        __syncthreads();   // all done reading old h0
        #pragma unroll
        for (int i = 0; i < 8; i++) {
            int r = rg * 8 + i;
            *reinterpret_cast<float2*>(As + r * ASTR + 160 + ch * 64 + 2 * cg) =
                make_float2(hstA[i][0], hstA[i][1]);
            *reinterpret_cast<float2*>(As + r * ASTR + 160 + 128 + ch * 64 + 2 * cg) =
                make_float2(hstB[i][0], hstB[i][1]);
        }
        __syncthreads();

        // ===== layer 1 (K = 256 h0 + 256 h1) =====
        layer_pass<512, 160>(As, Cb, WtB, wtb_u32, 1024, 0,   256, tid, rg, ch, cg, next, buf, hstA);
        layer_pass<512, 160>(As, Cb, WtB, wtb_u32, 1024, 128, 256, tid, rg, ch, cg, next, buf, hstB);
        __syncthreads();   // all done reading old h1
        {
            float2 w0 = *reinterpret_cast<const float2*>(Wfc + t * 256 + ch * 64 + 2 * cg);
            float2 w1 = *reinterpret_cast<const float2*>(Wfc + t * 256 + 128 + ch * 64 + 2 * cg);
            #pragma unroll
            for (int i = 0; i < 8; i++) {
                int r = rg * 8 + i;
                *reinterpret_cast<float2*>(As + r * ASTR + 416 + ch * 64 + 2 * cg) =
                    make_float2(hstA[i][0], hstA[i][1]);
                *reinterpret_cast<float2*>(As + r * ASTR + 416 + 128 + ch * 64 + 2 * cg) =
                    make_float2(hstB[i][0], hstB[i][1]);
                fcacc[i] += hstA[i][0] * w0.x + hstA[i][1] * w0.y
                          + hstB[i][0] * w1.x + hstB[i][1] * w1.y;
            }
        }
        __syncthreads();
    }

    asm volatile("cp.async.wait_group 0;" ::: "memory");

    #pragma unroll
    for (int i = 0; i < 8; i++) {
        #pragma unroll
        for (int off = 16; off > 0; off >>= 1)
            fcacc[i] += __shfl_xor_sync(0xffffffffu, fcacc[i], off);
    }
    if (cg == 0) {
        #pragma unroll
        for (int i = 0; i < 8; i++)
            Fp[(rg * 8 + i) * 2 + ch] = fcacc[i];
    }
    __syncthreads();
    if (tid < 32) {
        float v = Fp[tid * 2] + Fp[tid * 2 + 1] + bfc[0];
        out[rbase + tid] = sigf(v);
    }
}

extern "C" void kernel_launch(void* const* d_in, const int* in_sizes, int n_in,
                              void* d_out, int out_size) {
    const float* x    = (const float*)d_in[0];
    const float* Wih0 = (const float*)d_in[1];
    const float* Whh0 = (const float*)d_in[2];
    const float* bih0 = (const float*)d_in[3];
    const float* bhh0 = (const float*)d_in[4];
    const float* Wih1 = (const float*)d_in[5];
    const float* Whh1 = (const float*)d_in[6];
    const float* bih1 = (const float*)d_in[7];
    const float* bhh1 = (const float*)d_in[8];
    const float* Wfc  = (const float*)d_in[9];
    const float* bfc  = (const float*)d_in[10];
    float* out = (float*)d_out;

    int B = in_sizes[0] / (10 * 160);
    int grid = B / 32;

    prep_weights<<<(NTILES * TK * 512 + 255) / 256, 256>>>(Wih0, Whh0, Wih1, Whh1);
    prep_bias<<<8, 256>>>(bih0, bhh0, bih1, bhh1);

    size_t shmem = (size_t)(32 * ASTR + 32 * 512 + 2 * TILE_FLOATS + 64) * sizeof(float);
    cudaFuncSetAttribute(lstm_fused_kernel,
                         cudaFuncAttributeMaxDynamicSharedMemorySize, (int)shmem);

    lstm_fused_kernel<<<grid, NTHR, shmem>>>(x, Wfc, bfc, out);
}

// round 6
// speedup vs baseline: 2.2677x; 1.0003x over previous
#include <cuda_runtime.h>
#include <cstdint>

// Fused 2-layer LSTM + FC head. B=16384, T=10, IN=160, H=256.
// CTA = 32 batch rows, 256 threads. Weights are pre-transposed once per launch
// into Wprep (device global) in the exact smem-tile image the compute loop
// consumes, then streamed tile-by-tile with double-buffered cp.async.cg.
// Inner math: packed fma.rn.f32x2, 8 rows x 8 gate-cols per thread.

#define ASTR  676                 // A row stride: 160 x | 256 h0 | 256 h1 | pad
#define WTS2  520                 // W tile row stride (16B-aligned: 2080 B)
#define TK    16                  // k rows per tile
#define TILE_FLOATS (TK * WTS2)   // 8320 floats = 33280 B
#define TILE_CHUNKS (TILE_FLOATS / 4)  // 2080 x 16B
#define NTILES 116                // 26+26+32+32 per step
#define NTHR  256

__device__ __align__(16) float Wprep[NTILES * TILE_FLOATS];
__device__ float Bsum[2048];

typedef unsigned long long u64;

__device__ __forceinline__ u64 packdup(float x) {
    u64 r; asm("mov.b64 %0, {%1, %1};" : "=l"(r) : "f"(x)); return r;
}
__device__ __forceinline__ u64 pack2(float x, float y) {
    u64 r; asm("mov.b64 %0, {%1, %2};" : "=l"(r) : "f"(x), "f"(y)); return r;
}
__device__ __forceinline__ float2 unpack2(u64 v) {
    float2 f; asm("mov.b64 {%0, %1}, %2;" : "=f"(f.x), "=f"(f.y) : "l"(v)); return f;
}
__device__ __forceinline__ void fma2(u64& d, u64 a, u64 b) {
    asm("fma.rn.f32x2 %0, %1, %2, %0;" : "+l"(d) : "l"(a), "l"(b));
}
__device__ __forceinline__ float tanh_ap(float x) {
    float y; asm("tanh.approx.f32 %0, %1;" : "=f"(y) : "f"(x)); return y;
}
__device__ __forceinline__ float sigf(float x) {
    return fmaf(0.5f, tanh_ap(0.5f * x), 0.5f);
}
__device__ __forceinline__ float f4c(const float4& v, int c) {
    return c == 0 ? v.x : (c == 1 ? v.y : (c == 2 ? v.z : v.w));
}
__device__ __forceinline__ uint32_t smem_u32(const void* p) {
    uint32_t a;
    asm("{ .reg .u64 t; cvta.to.shared.u64 t, %1; cvt.u32.u64 %0, t; }"
        : "=r"(a) : "l"(p));
    return a;
}

// ---------------- prep kernels (run once per launch) ----------------

__global__ void prep_weights(const float* __restrict__ Wih0,
                             const float* __restrict__ Whh0,
                             const float* __restrict__ Wih1,
                             const float* __restrict__ Whh1) {
    int idx = blockIdx.x * blockDim.x + threadIdx.x;
    if (idx >= NTILES * TK * 512) return;
    int m  = idx & 511;
    int kk = (idx >> 9) & 15;
    int ti = idx >> 13;

    int layer, jb, kb;
    if      (ti < 26) { layer = 0; jb = 0;   kb = ti * 16; }
    else if (ti < 52) { layer = 0; jb = 128; kb = (ti - 26) * 16; }
    else if (ti < 84) { layer = 1; jb = 0;   kb = (ti - 52) * 16; }
    else              { layer = 1; jb = 128; kb = (ti - 84) * 16; }

    int seg = m >> 6, q = seg & 3, chq = seg >> 2;
    int e = m & 63, cgl = e >> 1, j = e & 1;
    int gate = (q & 1) * 2 + j;
    int gcol = gate * 256 + jb + chq * 64 + 2 * cgl + (q >> 1);
    int kglob = kb + kk;

    float v;
    if (layer == 0)
        v = (kglob < 160) ? Wih0[gcol * 160 + kglob]
                          : Whh0[gcol * 256 + (kglob - 160)];
    else
        v = (kglob < 256) ? Wih1[gcol * 256 + kglob]
                          : Whh1[gcol * 256 + (kglob - 256)];
    Wprep[(size_t)ti * TILE_FLOATS + kk * WTS2 + m] = v;
}

__global__ void prep_bias(const float* __restrict__ bih0, const float* __restrict__ bhh0,
                          const float* __restrict__ bih1, const float* __restrict__ bhh1) {
    int i = blockIdx.x * blockDim.x + threadIdx.x;
    if (i < 1024)      Bsum[i] = bih0[i] + bhh0[i];
    else if (i < 2048) Bsum[i] = bih1[i - 1024] + bhh1[i - 1024];
}

// ---------------- main kernel ----------------

__device__ __forceinline__ void issue_tile(uint32_t wtb_u32, int buf, int tile, int tid) {
    const float* src = Wprep + (size_t)tile * TILE_FLOATS;
    uint32_t dst = wtb_u32 + (uint32_t)buf * (TILE_FLOATS * 4);
    #pragma unroll
    for (int c = 0; c < 9; c++) {
        int off = tid + c * NTHR;
        if (off < TILE_CHUNKS) {
            asm volatile("cp.async.cg.shared.global [%0], [%1], 16;"
                :: "r"(dst + (uint32_t)off * 16), "l"(src + off * 4) : "memory");
        }
    }
    asm volatile("cp.async.commit_group;" ::: "memory");
}

// One output-column pass (128 gate-cols x 4 gates) of one LSTM layer.
template<int KTOT, int ABASE>
__device__ __forceinline__ void layer_pass(
    const float* __restrict__ As, float* __restrict__ Cb,
    const float* __restrict__ WtB, uint32_t wtb_u32,
    int bsoff, int jb, int cboff,
    int tid, int rg, int ch, int cg,
    int& next, int& buf, float (&hst)[8][2])
{
    u64 acc[32];
    {
        u64 pq[4];
        #pragma unroll
        for (int q = 0; q < 4; q++) {
            int hc = jb + ch * 64 + 2 * cg + (q >> 1);
            int g0 = ((q & 1) * 2) * 256 + hc;
            pq[q] = pack2(Bsum[bsoff + g0], Bsum[bsoff + g0 + 256]);
        }
        #pragma unroll
        for (int i = 0; i < 8; i++)
            #pragma unroll
            for (int q = 0; q < 4; q++)
                acc[i * 4 + q] = pq[q];
    }

    const float* ab0 = As + (rg * 8) * ASTR + ABASE;
    const float* wb0 = WtB + ch * 256 + 2 * cg;

    for (int kb = 0; kb < KTOT; kb += TK) {
        asm volatile("cp.async.wait_group 0;" ::: "memory");
        __syncthreads();                       // tile[buf] ready; prev compute done
        issue_tile(wtb_u32, buf ^ 1, next, tid);
        next = (next + 1 == NTILES) ? 0 : next + 1;

        const float* wbase = wb0 + buf * TILE_FLOATS;
        const float* ab = ab0 + kb;
        #pragma unroll
        for (int kq = 0; kq < 4; kq++) {
            float4 av[8];
            #pragma unroll
            for (int i = 0; i < 8; i++)
                av[i] = *reinterpret_cast<const float4*>(ab + i * ASTR + kq * 4);
            #pragma unroll
            for (int c = 0; c < 4; c++) {
                const u64* bp = reinterpret_cast<const u64*>(wbase + (kq * 4 + c) * WTS2);
                u64 b0 = bp[0], b1 = bp[32], b2 = bp[64], b3 = bp[96];
                #pragma unroll
                for (int i = 0; i < 8; i++) {
                    u64 ap = packdup(f4c(av[i], c));
                    fma2(acc[i * 4 + 0], ap, b0);
                    fma2(acc[i * 4 + 1], ap, b1);
                    fma2(acc[i * 4 + 2], ap, b2);
                    fma2(acc[i * 4 + 3], ap, b3);
                }
            }
        }
        buf ^= 1;
    }

    // epilogue: activations + cell update (exclusive (row,hcol) ownership)
    #pragma unroll
    for (int i = 0; i < 8; i++) {
        const int r = rg * 8 + i;
        #pragma unroll
        for (int hh = 0; hh < 2; hh++) {
            float2 pif = unpack2(acc[i * 4 + 2 * hh]);      // (i, f)
            float2 pgo = unpack2(acc[i * 4 + 2 * hh + 1]);  // (g, o)
            float iv = sigf(pif.x);
            float fv = sigf(pif.y);
            float gv = tanh_ap(pgo.x);
            float ov = sigf(pgo.y);
            int hcol = jb + ch * 64 + 2 * cg + hh;
            float* cc = Cb + r * 512 + cboff + hcol;
            float c = fv * cc[0] + iv * gv;
            cc[0] = c;
            hst[i][hh] = ov * tanh_ap(c);
        }
    }
}

__global__ void __launch_bounds__(NTHR, 1)
lstm_fused_kernel(
    const float* __restrict__ x,
    const float* __restrict__ Wfc, const float* __restrict__ bfc,
    float* __restrict__ out)
{
    extern __shared__ float sm[];
    float* As  = sm;                        // [32][676]
    float* Cb  = As + 32 * ASTR;            // [32][512] c0|c1
    float* WtB = Cb + 32 * 512;             // 2 x tile
    float* Fp  = WtB + 2 * TILE_FLOATS;     // [32][2]

    const int tid = threadIdx.x;
    const int wid = tid >> 5;
    const int rg  = wid & 3;
    const int ch  = wid >> 2;
    const int cg  = tid & 31;
    const int rbase = blockIdx.x * 32;
    const uint32_t wtb_u32 = smem_u32(WtB);

    int next = 1, buf = 0;
    issue_tile(wtb_u32, 0, 0, tid);        // prologue prefetch of tile 0

    for (int idx = tid; idx < 32 * ASTR; idx += NTHR) As[idx] = 0.0f;
    for (int idx = tid; idx < 32 * 512;  idx += NTHR) Cb[idx] = 0.0f;
    __syncthreads();

    float hstA[8][2], hstB[8][2];
    float fcacc[8];
    #pragma unroll
    for (int i = 0; i < 8; i++) fcacc[i] = 0.0f;

    for (int t = 0; t < 10; t++) {
        // stage x_t (coalesced; made visible by first in-loop barrier)
        for (int f = tid; f < 32 * 40; f += NTHR) {
            int row = f / 40, c4 = f % 40;
            float4 v = *reinterpret_cast<const float4*>(
                x + (size_t)(rbase + row) * 1600 + t * 160 + c4 * 4);
            *reinterpret_cast<float4*>(As + row * ASTR + c4 * 4) = v;
        }

        // ===== layer 0 (K = 160 x + 256 h0) =====
        layer_pass<416, 0>(As, Cb, WtB, wtb_u32, 0, 0,   0, tid, rg, ch, cg, next, buf, hstA);
        layer_pass<416, 0>(As, Cb, WtB, wtb_u32, 0, 128, 0, tid, rg, ch, cg, next, buf, hstB);
        __syncthreads();   // all done reading old h0
        #pragma unroll
        for (int i = 0; i < 8; i++) {
            int r = rg * 8 + i;
            *reinterpret_cast<float2*>(As + r * ASTR + 160 + ch * 64 + 2 * cg) =
                make_float2(hstA[i][0], hstA[i][1]);
            *reinterpret_cast<float2*>(As + r * ASTR + 160 + 128 + ch * 64 + 2 * cg) =
                make_float2(hstB[i][0], hstB[i][1]);
        }
        __syncthreads();

        // ===== layer 1 (K = 256 h0 + 256 h1) =====
        layer_pass<512, 160>(As, Cb, WtB, wtb_u32, 1024, 0,   256, tid, rg, ch, cg, next, buf, hstA);
        layer_pass<512, 160>(As, Cb, WtB, wtb_u32, 1024, 128, 256, tid, rg, ch, cg, next, buf, hstB);
        __syncthreads();   // all done reading old h1
        {
            float2 w0 = *reinterpret_cast<const float2*>(Wfc + t * 256 + ch * 64 + 2 * cg);
            float2 w1 = *reinterpret_cast<const float2*>(Wfc + t * 256 + 128 + ch * 64 + 2 * cg);
            #pragma unroll
            for (int i = 0; i < 8; i++) {
                int r = rg * 8 + i;
                *reinterpret_cast<float2*>(As + r * ASTR + 416 + ch * 64 + 2 * cg) =
                    make_float2(hstA[i][0], hstA[i][1]);
                *reinterpret_cast<float2*>(As + r * ASTR + 416 + 128 + ch * 64 + 2 * cg) =
                    make_float2(hstB[i][0], hstB[i][1]);
                fcacc[i] += hstA[i][0] * w0.x + hstA[i][1] * w0.y
                          + hstB[i][0] * w1.x + hstB[i][1] * w1.y;
            }
        }
        __syncthreads();
    }

    asm volatile("cp.async.wait_group 0;" ::: "memory");

    #pragma unroll
    for (int i = 0; i < 8; i++) {
        #pragma unroll
        for (int off = 16; off > 0; off >>= 1)
            fcacc[i] += __shfl_xor_sync(0xffffffffu, fcacc[i], off);
    }
    if (cg == 0) {
        #pragma unroll
        for (int i = 0; i < 8; i++)
            Fp[(rg * 8 + i) * 2 + ch] = fcacc[i];
    }
    __syncthreads();
    if (tid < 32) {
        float v = Fp[tid * 2] + Fp[tid * 2 + 1] + bfc[0];
        out[rbase + tid] = sigf(v);
    }
}

extern "C" void kernel_launch(void* const* d_in, const int* in_sizes, int n_in,
                              void* d_out, int out_size) {
    const float* x    = (const float*)d_in[0];
    const float* Wih0 = (const float*)d_in[1];
    const float* Whh0 = (const float*)d_in[2];
    const float* bih0 = (const float*)d_in[3];
    const float* bhh0 = (const float*)d_in[4];
    const float* Wih1 = (const float*)d_in[5];
    const float* Whh1 = (const float*)d_in[6];
    const float* bih1 = (const float*)d_in[7];
    const float* bhh1 = (const float*)d_in[8];
    const float* Wfc  = (const float*)d_in[9];
    const float* bfc  = (const float*)d_in[10];
    float* out = (float*)d_out;

    int B = in_sizes[0] / (10 * 160);
    int grid = B / 32;

    prep_weights<<<(NTILES * TK * 512 + 255) / 256, 256>>>(Wih0, Whh0, Wih1, Whh1);
    prep_bias<<<8, 256>>>(bih0, bhh0, bih1, bhh1);

    size_t shmem = (size_t)(32 * ASTR + 32 * 512 + 2 * TILE_FLOATS + 64) * sizeof(float);
    cudaFuncSetAttribute(lstm_fused_kernel,
                         cudaFuncAttributeMaxDynamicSharedMemorySize, (int)shmem);

    lstm_fused_kernel<<<grid, NTHR, shmem>>>(x, Wfc, bfc, out);
}

// round 7
// speedup vs baseline: 2.2679x; 1.0001x over previous
#include <cuda_runtime.h>
#include <cstdint>

// Fused 2-layer LSTM + FC head. B=16384, T=10, IN=160, H=256.
// CTA = 32 batch rows, 256 threads. Weights are pre-transposed once per launch
// into Wprep (device global) in the exact smem-tile image the compute loop
// consumes, then streamed tile-by-tile with double-buffered cp.async.cg.
// Inner math: packed fma.rn.f32x2, 8 rows x 8 gate-cols per thread.

#define ASTR  676                 // A row stride: 160 x | 256 h0 | 256 h1 | pad
#define WTS2  520                 // W tile row stride (16B-aligned: 2080 B)
#define TK    16                  // k rows per tile
#define TILE_FLOATS (TK * WTS2)   // 8320 floats = 33280 B
#define TILE_CHUNKS (TILE_FLOATS / 4)  // 2080 x 16B
#define NTILES 116                // 26+26+32+32 per step
#define NTHR  256

__device__ __align__(16) float Wprep[NTILES * TILE_FLOATS];
__device__ float Bsum[2048];

typedef unsigned long long u64;

__device__ __forceinline__ u64 packdup(float x) {
    u64 r; asm("mov.b64 %0, {%1, %1};" : "=l"(r) : "f"(x)); return r;
}
__device__ __forceinline__ u64 pack2(float x, float y) {
    u64 r; asm("mov.b64 %0, {%1, %2};" : "=l"(r) : "f"(x), "f"(y)); return r;
}
__device__ __forceinline__ float2 unpack2(u64 v) {
    float2 f; asm("mov.b64 {%0, %1}, %2;" : "=f"(f.x), "=f"(f.y) : "l"(v)); return f;
}
__device__ __forceinline__ void fma2(u64& d, u64 a, u64 b) {
    asm("fma.rn.f32x2 %0, %1, %2, %0;" : "+l"(d) : "l"(a), "l"(b));
}
__device__ __forceinline__ float tanh_ap(float x) {
    float y; asm("tanh.approx.f32 %0, %1;" : "=f"(y) : "f"(x)); return y;
}
__device__ __forceinline__ float sigf(float x) {
    return fmaf(0.5f, tanh_ap(0.5f * x), 0.5f);
}
__device__ __forceinline__ float f4c(const float4& v, int c) {
    return c == 0 ? v.x : (c == 1 ? v.y : (c == 2 ? v.z : v.w));
}
__device__ __forceinline__ uint32_t smem_u32(const void* p) {
    uint32_t a;
    asm("{ .reg .u64 t; cvta.to.shared.u64 t, %1; cvt.u32.u64 %0, t; }"
        : "=r"(a) : "l"(p));
    return a;
}

// ---------------- prep kernels (run once per launch) ----------------

__global__ void prep_weights(const float* __restrict__ Wih0,
                             const float* __restrict__ Whh0,
                             const float* __restrict__ Wih1,
                             const float* __restrict__ Whh1) {
    int idx = blockIdx.x * blockDim.x + threadIdx.x;
    if (idx >= NTILES * TK * 512) return;
    int m  = idx & 511;
    int kk = (idx >> 9) & 15;
    int ti = idx >> 13;

    int layer, jb, kb;
    if      (ti < 26) { layer = 0; jb = 0;   kb = ti * 16; }
    else if (ti < 52) { layer = 0; jb = 128; kb = (ti - 26) * 16; }
    else if (ti < 84) { layer = 1; jb = 0;   kb = (ti - 52) * 16; }
    else              { layer = 1; jb = 128; kb = (ti - 84) * 16; }

    int seg = m >> 6, q = seg & 3, chq = seg >> 2;
    int e = m & 63, cgl = e >> 1, j = e & 1;
    int gate = (q & 1) * 2 + j;
    int gcol = gate * 256 + jb + chq * 64 + 2 * cgl + (q >> 1);
    int kglob = kb + kk;

    float v;
    if (layer == 0)
        v = (kglob < 160) ? Wih0[gcol * 160 + kglob]
                          : Whh0[gcol * 256 + (kglob - 160)];
    else
        v = (kglob < 256) ? Wih1[gcol * 256 + kglob]
                          : Whh1[gcol * 256 + (kglob - 256)];
    Wprep[(size_t)ti * TILE_FLOATS + kk * WTS2 + m] = v;
}

__global__ void prep_bias(const float* __restrict__ bih0, const float* __restrict__ bhh0,
                          const float* __restrict__ bih1, const float* __restrict__ bhh1) {
    int i = blockIdx.x * blockDim.x + threadIdx.x;
    if (i < 1024)      Bsum[i] = bih0[i] + bhh0[i];
    else if (i < 2048) Bsum[i] = bih1[i - 1024] + bhh1[i - 1024];
}

// ---------------- main kernel ----------------

__device__ __forceinline__ void issue_tile(uint32_t wtb_u32, int buf, int tile, int tid) {
    const float* src = Wprep + (size_t)tile * TILE_FLOATS;
    uint32_t dst = wtb_u32 + (uint32_t)buf * (TILE_FLOATS * 4);
    #pragma unroll
    for (int c = 0; c < 9; c++) {
        int off = tid + c * NTHR;
        if (off < TILE_CHUNKS) {
            asm volatile("cp.async.cg.shared.global [%0], [%1], 16;"
                :: "r"(dst + (uint32_t)off * 16), "l"(src + off * 4) : "memory");
        }
    }
    asm volatile("cp.async.commit_group;" ::: "memory");
}

// One output-column pass (128 gate-cols x 4 gates) of one LSTM layer.
template<int KTOT, int ABASE>
__device__ __forceinline__ void layer_pass(
    const float* __restrict__ As, float* __restrict__ Cb,
    const float* __restrict__ WtB, uint32_t wtb_u32,
    int bsoff, int jb, int cboff,
    int tid, int rg, int ch, int cg,
    int& next, int& buf, float (&hst)[8][2])
{
    u64 acc[32];
    {
        u64 pq[4];
        #pragma unroll
        for (int q = 0; q < 4; q++) {
            int hc = jb + ch * 64 + 2 * cg + (q >> 1);
            int g0 = ((q & 1) * 2) * 256 + hc;
            pq[q] = pack2(Bsum[bsoff + g0], Bsum[bsoff + g0 + 256]);
        }
        #pragma unroll
        for (int i = 0; i < 8; i++)
            #pragma unroll
            for (int q = 0; q < 4; q++)
                acc[i * 4 + q] = pq[q];
    }

    const float* ab0 = As + (rg * 8) * ASTR + ABASE;
    const float* wb0 = WtB + ch * 256 + 2 * cg;

    for (int kb = 0; kb < KTOT; kb += TK) {
        asm volatile("cp.async.wait_group 0;" ::: "memory");
        __syncthreads();                       // tile[buf] ready; prev compute done
        issue_tile(wtb_u32, buf ^ 1, next, tid);
        next = (next + 1 == NTILES) ? 0 : next + 1;

        const float* wbase = wb0 + buf * TILE_FLOATS;
        const float* ab = ab0 + kb;
        #pragma unroll
        for (int kq = 0; kq < 4; kq++) {
            float4 av[8];
            #pragma unroll
            for (int i = 0; i < 8; i++)
                av[i] = *reinterpret_cast<const float4*>(ab + i * ASTR + kq * 4);
            #pragma unroll
            for (int c = 0; c < 4; c++) {
                const u64* bp = reinterpret_cast<const u64*>(wbase + (kq * 4 + c) * WTS2);
                u64 b0 = bp[0], b1 = bp[32], b2 = bp[64], b3 = bp[96];
                #pragma unroll
                for (int i = 0; i < 8; i++) {
                    u64 ap = packdup(f4c(av[i], c));
                    fma2(acc[i * 4 + 0], ap, b0);
                    fma2(acc[i * 4 + 1], ap, b1);
                    fma2(acc[i * 4 + 2], ap, b2);
                    fma2(acc[i * 4 + 3], ap, b3);
                }
            }
        }
        buf ^= 1;
    }

    // epilogue: activations + cell update (exclusive (row,hcol) ownership)
    #pragma unroll
    for (int i = 0; i < 8; i++) {
        const int r = rg * 8 + i;
        #pragma unroll
        for (int hh = 0; hh < 2; hh++) {
            float2 pif = unpack2(acc[i * 4 + 2 * hh]);      // (i, f)
            float2 pgo = unpack2(acc[i * 4 + 2 * hh + 1]);  // (g, o)
            float iv = sigf(pif.x);
            float fv = sigf(pif.y);
            float gv = tanh_ap(pgo.x);
            float ov = sigf(pgo.y);
            int hcol = jb + ch * 64 + 2 * cg + hh;
            float* cc = Cb + r * 512 + cboff + hcol;
            float c = fv * cc[0] + iv * gv;
            cc[0] = c;
            hst[i][hh] = ov * tanh_ap(c);
        }
    }
}

__global__ void __launch_bounds__(NTHR, 1)
lstm_fused_kernel(
    const float* __restrict__ x,
    const float* __restrict__ Wfc, const float* __restrict__ bfc,
    float* __restrict__ out)
{
    extern __shared__ float sm[];
    float* As  = sm;                        // [32][676]
    float* Cb  = As + 32 * ASTR;            // [32][512] c0|c1
    float* WtB = Cb + 32 * 512;             // 2 x tile
    float* Fp  = WtB + 2 * TILE_FLOATS;     // [32][2]

    const int tid = threadIdx.x;
    const int wid = tid >> 5;
    const int rg  = wid & 3;
    const int ch  = wid >> 2;
    const int cg  = tid & 31;
    const int rbase = blockIdx.x * 32;
    const uint32_t wtb_u32 = smem_u32(WtB);

    int next = 1, buf = 0;
    issue_tile(wtb_u32, 0, 0, tid);        // prologue prefetch of tile 0

    for (int idx = tid; idx < 32 * ASTR; idx += NTHR) As[idx] = 0.0f;
    for (int idx = tid; idx < 32 * 512;  idx += NTHR) Cb[idx] = 0.0f;
    __syncthreads();

    float hstA[8][2], hstB[8][2];
    float fcacc[8];
    #pragma unroll
    for (int i = 0; i < 8; i++) fcacc[i] = 0.0f;

    for (int t = 0; t < 10; t++) {
        // stage x_t (coalesced; made visible by first in-loop barrier)
        for (int f = tid; f < 32 * 40; f += NTHR) {
            int row = f / 40, c4 = f % 40;
            float4 v = *reinterpret_cast<const float4*>(
                x + (size_t)(rbase + row) * 1600 + t * 160 + c4 * 4);
            *reinterpret_cast<float4*>(As + row * ASTR + c4 * 4) = v;
        }

        // ===== layer 0 (K = 160 x + 256 h0) =====
        layer_pass<416, 0>(As, Cb, WtB, wtb_u32, 0, 0,   0, tid, rg, ch, cg, next, buf, hstA);
        layer_pass<416, 0>(As, Cb, WtB, wtb_u32, 0, 128, 0, tid, rg, ch, cg, next, buf, hstB);
        __syncthreads();   // all done reading old h0
        #pragma unroll
        for (int i = 0; i < 8; i++) {
            int r = rg * 8 + i;
            *reinterpret_cast<float2*>(As + r * ASTR + 160 + ch * 64 + 2 * cg) =
                make_float2(hstA[i][0], hstA[i][1]);
            *reinterpret_cast<float2*>(As + r * ASTR + 160 + 128 + ch * 64 + 2 * cg) =
                make_float2(hstB[i][0], hstB[i][1]);
        }
        __syncthreads();

        // ===== layer 1 (K = 256 h0 + 256 h1) =====
        layer_pass<512, 160>(As, Cb, WtB, wtb_u32, 1024, 0,   256, tid, rg, ch, cg, next, buf, hstA);
        layer_pass<512, 160>(As, Cb, WtB, wtb_u32, 1024, 128, 256, tid, rg, ch, cg, next, buf, hstB);
        __syncthreads();   // all done reading old h1
        {
            float2 w0 = *reinterpret_cast<const float2*>(Wfc + t * 256 + ch * 64 + 2 * cg);
            float2 w1 = *reinterpret_cast<const float2*>(Wfc + t * 256 + 128 + ch * 64 + 2 * cg);
            #pragma unroll
            for (int i = 0; i < 8; i++) {
                int r = rg * 8 + i;
                *reinterpret_cast<float2*>(As + r * ASTR + 416 + ch * 64 + 2 * cg) =
                    make_float2(hstA[i][0], hstA[i][1]);
                *reinterpret_cast<float2*>(As + r * ASTR + 416 + 128 + ch * 64 + 2 * cg) =
                    make_float2(hstB[i][0], hstB[i][1]);
                fcacc[i] += hstA[i][0] * w0.x + hstA[i][1] * w0.y
                          + hstB[i][0] * w1.x + hstB[i][1] * w1.y;
            }
        }
        __syncthreads();
    }

    asm volatile("cp.async.wait_group 0;" ::: "memory");

    #pragma unroll
    for (int i = 0; i < 8; i++) {
        #pragma unroll
        for (int off = 16; off > 0; off >>= 1)
            fcacc[i] += __shfl_xor_sync(0xffffffffu, fcacc[i], off);
    }
    if (cg == 0) {
        #pragma unroll
        for (int i = 0; i < 8; i++)
            Fp[(rg * 8 + i) * 2 + ch] = fcacc[i];
    }
    __syncthreads();
    if (tid < 32) {
        float v = Fp[tid * 2] + Fp[tid * 2 + 1] + bfc[0];
        out[rbase + tid] = sigf(v);
    }
}

extern "C" void kernel_launch(void* const* d_in, const int* in_sizes, int n_in,
                              void* d_out, int out_size) {
    const float* x    = (const float*)d_in[0];
    const float* Wih0 = (const float*)d_in[1];
    const float* Whh0 = (const float*)d_in[2];
    const float* bih0 = (const float*)d_in[3];
    const float* bhh0 = (const float*)d_in[4];
    const float* Wih1 = (const float*)d_in[5];
    const float* Whh1 = (const float*)d_in[6];
    const float* bih1 = (const float*)d_in[7];
    const float* bhh1 = (const float*)d_in[8];
    const float* Wfc  = (const float*)d_in[9];
    const float* bfc  = (const float*)d_in[10];
    float* out = (float*)d_out;

    int B = in_sizes[0] / (10 * 160);
    int grid = B / 32;

    prep_weights<<<(NTILES * TK * 512 + 255) / 256, 256>>>(Wih0, Whh0, Wih1, Whh1);
    prep_bias<<<8, 256>>>(bih0, bhh0, bih1, bhh1);

    size_t shmem = (size_t)(32 * ASTR + 32 * 512 + 2 * TILE_FLOATS + 64) * sizeof(float);
    cudaFuncSetAttribute(lstm_fused_kernel,
                         cudaFuncAttributeMaxDynamicSharedMemorySize, (int)shmem);

    lstm_fused_kernel<<<grid, NTHR, shmem>>>(x, Wfc, bfc, out);
}